// round 15
// baseline (speedup 1.0000x reference)
#include <cuda_runtime.h>
#include <math.h>
#include <limits.h>

#define NIMG 4
#define NPRI 3106
#define NCLS 20      // classes 1..20 (background excluded)
#define NTOT 21
#define NPAD 4096    // max pow2 bound for sort array
#define TOPK 200

#define MIN_SCORE 0.05f
#define MAX_OVERLAP 0.45f

#define NMS_NT 1024
#define NWARPS (NMS_NT / 32)   // 32

#define CHUNK 128
#define CW 4                  // CHUNK/32 words

// ---------------- device scratch (no allocations allowed) ----------------
__device__ float  g_cls[NIMG][NCLS][NPRI];      // class-major probs
__device__ float4 g_box[NIMG][NPRI];            // decoded boxes x1,y1,x2,y2
__device__ float  g_candScore[NIMG][NCLS][TOPK];
__device__ float4 g_candBox[NIMG][NCLS][TOPK];
__device__ int    g_candCnt[NIMG][NCLS];

// Accurate fp32 exp via fp64 range-reduction + compensated (double-float)
// fp32 Horner. Relative error ~2^-45. Immune to fast-math. |x| <= 85.
__device__ __forceinline__ float exp_ff(float x)
{
    float nf = rintf(x * 1.4426950408889634f);
    double rd = fma((double)nf, -0.6931471805599453, (double)x);
    float rh = (float)rd;
    float rl = (float)(rd - (double)rh);

    float t;
    t = 2.0876756987868099e-9f;                    // 1/12!
    t = fmaf(t, rh, 2.5052108385441720e-8f);       // 1/11!
    t = fmaf(t, rh, 2.7557319223985893e-7f);       // 1/10!
    t = fmaf(t, rh, 2.7557319223985888e-6f);       // 1/9!
    t = fmaf(t, rh, 2.4801587301587302e-5f);       // 1/8!
    t = fmaf(t, rh, 1.9841269841269841e-4f);       // 1/7!

    const float C[7] = { 1.3888888888888889e-3f,
                         8.3333333333333332e-3f,
                         4.1666666666666664e-2f,
                         1.6666666666666666e-1f,
                         0.5f, 1.0f, 1.0f };
    float ah = t, al = 0.0f;
    #pragma unroll
    for (int k = 0; k < 7; k++) {
        float ph = __fmul_rn(ah, rh);
        float pl = fmaf(ah, rh, -ph);
        pl = fmaf(al, rh, pl);
        float ck = C[k];
        float sh = __fadd_rn(ck, ph);
        float sl = __fsub_rn(ph, __fsub_rn(sh, ck));
        al = __fadd_rn(pl, sl);
        ah = sh;
    }
    float res = __fadd_rn(fmaf(ah, rl, al), ah);
    return res * __int_as_float(((int)nf + 127) << 23);
}

// ---------------- kernel 1: softmax + box decode (2 threads per row) ----------
__global__ void __launch_bounds__(64, 1)
softmax_decode_kernel(const float* __restrict__ locs,
                      const float* __restrict__ scores,
                      const float* __restrict__ priors)
{
    int gid  = blockIdx.x * blockDim.x + threadIdx.x;
    int row  = gid >> 1;
    int half = gid & 1;
    bool real = (row < NIMG * NPRI);
    if (!real) row = NIMG * NPRI - 1;          // clamp; keep lanes alive for shfl
    int img = row / NPRI;
    int p   = row - img * NPRI;

    const float* s  = scores + (size_t)row * NTOT;
    const float* l  = locs   + (size_t)row * 4;
    const float* pr = priors + (size_t)p * 4;

    // half0: classes 0..10 (11), half1: classes 11..20 (10)
    int c0 = half ? 11 : 0;
    int cn = half ? 10 : 11;

    float zv[11];
    float m = -INFINITY;
    #pragma unroll
    for (int k = 0; k < 11; k++) {
        if (k < cn) { zv[k] = s[c0 + k]; m = fmaxf(m, zv[k]); }
    }
    m = fmaxf(m, __shfl_xor_sync(0xffffffffu, m, 1));

    float e[11];
    double dsum = 0.0;
    #pragma unroll
    for (int k = 0; k < 11; k++) {
        if (k < cn) { e[k] = exp_ff(zv[k] - m); dsum += (double)e[k]; }
    }
    // decode exp in parallel: half0 -> w, half1 -> h
    float dexp = half ? (exp_ff(__fdiv_rn(l[3], 5.0f)) * pr[3])
                      : (exp_ff(__fdiv_rn(l[2], 5.0f)) * pr[2]);

    dsum += __shfl_xor_sync(0xffffffffu, dsum, 1);
    float fsum = (float)dsum;

    if (real) {
        if (half == 0) {
            #pragma unroll
            for (int k = 1; k < 11; k++)          // skip background class 0
                g_cls[img][k - 1][p] = __fdiv_rn(e[k], fsum);
        } else {
            #pragma unroll
            for (int k = 0; k < 10; k++)
                g_cls[img][10 + k][p] = __fdiv_rn(e[k], fsum);
        }
    }

    float other = __shfl_xor_sync(0xffffffffu, dexp, 1);
    if (real && half == 0) {
        float w = dexp, h = other;
        float cx = __fdiv_rn(l[0] * pr[2], 10.0f) + pr[0];
        float cy = __fdiv_rn(l[1] * pr[3], 10.0f) + pr[1];
        float4 b;
        b.x = cx - __fdiv_rn(w, 2.0f);
        b.y = cy - __fdiv_rn(h, 2.0f);
        b.z = cx + __fdiv_rn(w, 2.0f);
        b.w = cy + __fdiv_rn(h, 2.0f);
        g_box[img][p] = b;
    }
}

// overlap test with precomputed areas; bit-identical to reference iou > T
__device__ __forceinline__ bool overlap_f(float4 a, float aA, float4 b, float aB)
{
    float dx = fminf(a.z, b.z) - fmaxf(a.x, b.x);
    float dy = fminf(a.w, b.w) - fmaxf(a.y, b.y);
    if (dx > 0.0f && dy > 0.0f) {
        float inter = dx * dy;
        return __fdiv_rn(inter, aA + aB - inter) > MAX_OVERLAP;
    }
    return false;   // inter==0 -> iou==0 <= T
}

// exclusive warp-count prefix via shfl scan; s_wcnt[lane] valid for lane<32.
__device__ __forceinline__ void scan_counts(const int* s_wcnt, int wid, int lane,
                                            int& wpre, int& wsum)
{
    int x = s_wcnt[lane];
    #pragma unroll
    for (int d = 1; d < 32; d <<= 1) {
        int v = __shfl_up_sync(0xffffffffu, x, d);
        if (lane >= d) x += v;
    }
    wsum = __shfl_sync(0xffffffffu, x, 31);
    wpre = (wid == 0) ? 0 : __shfl_sync(0xffffffffu, x, wid - 1);
}

// one register-resident bitonic micro-step on value v at element index e
__device__ __forceinline__ unsigned long long bitonic_reg_step(
    unsigned long long v, int e, int k, int j)
{
    unsigned long long pv = __shfl_xor_sync(0xffffffffu, v, j);
    bool down  = ((e & k) == 0);     // this region sorts descending
    bool lower = ((e & j) == 0);
    unsigned long long mx = (v > pv) ? v : pv;
    unsigned long long mn = (v > pv) ? pv : v;
    return (down == lower) ? mx : mn;
}

// ---------------- kernel 2: per-(image,class) greedy NMS ----------------
// Dynamic shared layout:
//   [0,      32768)   u64    skey64[NPAD]      (score_bits<<32 | ~idx)
//   [32768,  82464)   float4 sbox[NPRI]
//   [82464,  94888)   float  sscore[NPRI]
//   [94888, 107312)   float  sarea[NPRI]
#define SMEM_NMS_BYTES 107392

__global__ void __launch_bounds__(NMS_NT, 1)
nms_kernel()
{
    extern __shared__ char sm[];
    unsigned long long* skey64 = (unsigned long long*)(sm);
    float4*             sbox   = (float4*)(sm + 32768);
    float*              sscore = (float*)(sm + 82464);
    float*              sarea  = (float*)(sm + 94888);
    __shared__ int      s_wcnt[NWARPS];
    __shared__ unsigned s_row[CHUNK][CW];
    __shared__ unsigned s_keptw[CW];
    __shared__ int      s_nk;
    __shared__ float4   s_kbox[CHUNK];
    __shared__ float    s_karea[CHUNK];

    int img  = blockIdx.x / NCLS;
    int c    = blockIdx.x % NCLS;
    int tid  = threadIdx.x;
    int wid  = tid >> 5;
    int lane = tid & 31;
    unsigned lmask = (1u << lane) - 1u;

    // ---- Phase A: stable compaction of valid entries ----
    int base = 0;
    for (int bp = 0; bp < NPRI; bp += NMS_NT) {
        int p = bp + tid;
        float sc = (p < NPRI) ? g_cls[img][c][p] : 0.0f;
        bool ok = (p < NPRI) && (sc > MIN_SCORE);
        unsigned b = __ballot_sync(0xffffffffu, ok);
        if (lane == 0) s_wcnt[wid] = __popc(b);
        __syncthreads();
        int wpre, wsum;
        scan_counts(s_wcnt, wid, lane, wpre, wsum);
        int rank = base + wpre + __popc(b & lmask);
        if (ok)
            skey64[rank] = ((unsigned long long)__float_as_uint(sc) << 32)
                         | (unsigned int)(~p);
        base += wsum;
        __syncthreads();
    }
    int nvalid = base;

    int keptTotal = 0;

    if (nvalid > 0) {
        int npow = 32;
        while (npow < nvalid) npow <<= 1;
        for (int t = nvalid + tid; t < npow; t += NMS_NT)
            skey64[t] = 0ull;
        __syncthreads();

        // ---- Phase B: HYBRID bitonic sort (desc u64; score desc, idx asc) ----
        int nseg = (npow + NMS_NT - 1) / NMS_NT;

        // stages k = 2..32: entirely intra-warp (register + shfl)
        for (int q = 0; q < nseg; q++) {
            int e = q * NMS_NT + tid;
            if (e < npow) {               // whole warp uniform (npow % 32 == 0)
                unsigned long long v = skey64[e];
                #pragma unroll
                for (int k = 2; k <= 32; k <<= 1) {
                    #pragma unroll
                    for (int j = k >> 1; j >= 1; j >>= 1)
                        v = bitonic_reg_step(v, e, k, j);
                }
                skey64[e] = v;
            }
        }
        __syncthreads();

        // stages k = 64..npow: smem steps for j>=32, register tail j<=16
        for (int k = 64; k <= npow; k <<= 1) {
            for (int j = k >> 1; j >= 32; j >>= 1) {
                for (int t = tid; t < npow; t += NMS_NT) {
                    int l = t ^ j;
                    if (l > t) {
                        unsigned long long ka = skey64[t], kb = skey64[l];
                        bool asc = ((t & k) == 0);
                        if ((kb > ka) == asc) {
                            skey64[t] = kb;
                            skey64[l] = ka;
                        }
                    }
                }
                __syncthreads();
            }
            for (int q = 0; q < nseg; q++) {
                int e = q * NMS_NT + tid;
                if (e < npow) {
                    unsigned long long v = skey64[e];
                    #pragma unroll
                    for (int j = 16; j >= 1; j >>= 1)
                        v = bitonic_reg_step(v, e, k, j);
                    skey64[e] = v;
                }
            }
            __syncthreads();
        }

        // ---- Phase C: gather boxes + scores + areas ----
        for (int i = tid; i < nvalid; i += NMS_NT) {
            unsigned long long key = skey64[i];
            unsigned idx = ~((unsigned)key);
            float4 b = g_box[img][idx];
            sbox[i]   = b;
            sscore[i] = __uint_as_float((unsigned)(key >> 32));
            sarea[i]  = (b.z - b.x) * (b.w - b.y);
        }
        __syncthreads();

        // ---- Phase D: 128-wide chunked greedy ----
        int nrem = nvalid;
        while (nrem > 0 && keptTotal < TOPK) {
            int m = min(CHUNK, nrem);

            // 1) in-chunk upper-tri rows: warp `wid` computes rows wid, wid+32,
            //    wid+64, wid+96; each row = CW ballot words (bits j>r only).
            #pragma unroll
            for (int rr = 0; rr < CW; rr++) {
                int r = wid + (rr << 5);
                if (r < m) {
                    float4 bi = sbox[r];
                    float  ai = sarea[r];
                    #pragma unroll
                    for (int t = 0; t < CW; t++) {
                        int j = (t << 5) + lane;
                        bool ov = (j > r && j < m)
                                ? overlap_f(bi, ai, sbox[j], sarea[j]) : false;
                        unsigned w = __ballot_sync(0xffffffffu, ov);
                        if (lane == 0) s_row[r][t] = w;
                    }
                }
            }
            __syncthreads();

            // 2) warp 0: ballot resolve; lanes hold rows lane, lane+32,
            //    lane+64, lane+96 (register-resident). Iterations = nk only.
            if (wid == 0) {
                unsigned ra[CW] = {0u,0u,0u,0u};
                unsigned rb[CW] = {0u,0u,0u,0u};
                unsigned rc[CW] = {0u,0u,0u,0u};
                unsigned rd[CW] = {0u,0u,0u,0u};
                if (lane < m) {
                    #pragma unroll
                    for (int t = 0; t < CW; t++) ra[t] = s_row[lane][t];
                }
                if (lane + 32 < m) {
                    #pragma unroll
                    for (int t = 0; t < CW; t++) rb[t] = s_row[lane + 32][t];
                }
                if (lane + 64 < m) {
                    #pragma unroll
                    for (int t = 0; t < CW; t++) rc[t] = s_row[lane + 64][t];
                }
                if (lane + 96 < m) {
                    #pragma unroll
                    for (int t = 0; t < CW; t++) rd[t] = s_row[lane + 96][t];
                }
                unsigned unres[CW], kept[CW];
                #pragma unroll
                for (int t = 0; t < CW; t++) {
                    int lo = t << 5;
                    unres[t] = (m >= lo + 32) ? 0xffffffffu
                             : (m > lo) ? ((1u << (m - lo)) - 1u) : 0u;
                    kept[t] = 0u;
                }
                int nk = 0;
                while (true) {
                    int w = -1;
                    #pragma unroll
                    for (int t = CW - 1; t >= 0; t--)
                        if (unres[t]) w = t;
                    if (w < 0) break;
                    int bpos = __ffs(unres[w]) - 1;
                    int i = (w << 5) + bpos;
                    kept[w] |= 1u << bpos;
                    unres[w] &= ~(1u << bpos);
                    nk++;
                    int src = i & 31;
                    int grp = i >> 5;            // uniform
                    unsigned w0, w1, w2, w3;
                    if (grp == 0) {
                        w0 = __shfl_sync(0xffffffffu, ra[0], src);
                        w1 = __shfl_sync(0xffffffffu, ra[1], src);
                        w2 = __shfl_sync(0xffffffffu, ra[2], src);
                        w3 = __shfl_sync(0xffffffffu, ra[3], src);
                    } else if (grp == 1) {
                        w0 = __shfl_sync(0xffffffffu, rb[0], src);
                        w1 = __shfl_sync(0xffffffffu, rb[1], src);
                        w2 = __shfl_sync(0xffffffffu, rb[2], src);
                        w3 = __shfl_sync(0xffffffffu, rb[3], src);
                    } else if (grp == 2) {
                        w0 = __shfl_sync(0xffffffffu, rc[0], src);
                        w1 = __shfl_sync(0xffffffffu, rc[1], src);
                        w2 = __shfl_sync(0xffffffffu, rc[2], src);
                        w3 = __shfl_sync(0xffffffffu, rc[3], src);
                    } else {
                        w0 = __shfl_sync(0xffffffffu, rd[0], src);
                        w1 = __shfl_sync(0xffffffffu, rd[1], src);
                        w2 = __shfl_sync(0xffffffffu, rd[2], src);
                        w3 = __shfl_sync(0xffffffffu, rd[3], src);
                    }
                    unres[0] &= ~w0;
                    unres[1] &= ~w1;
                    unres[2] &= ~w2;
                    unres[3] &= ~w3;
                }
                if (lane < CW) s_keptw[lane] = kept[lane];
                if (lane == 0) s_nk = nk;
            }
            __syncthreads();

            int nk = s_nk;

            // 3) export kept + densify kept boxes via keptw ranks
            if (tid < m) {
                int w = tid >> 5;
                unsigned km = s_keptw[w];
                if ((km >> lane) & 1u) {
                    int rank = __popc(km & lmask);
                    for (int ww = 0; ww < w; ww++)
                        rank += __popc(s_keptw[ww]);
                    int slot = keptTotal + rank;
                    if (slot < TOPK) {
                        g_candScore[img][c][slot] = sscore[tid];
                        g_candBox[img][c][slot]   = sbox[tid];
                    }
                    s_kbox[rank]  = sbox[tid];
                    s_karea[rank] = sarea[tid];
                }
            }
            keptTotal += nk;
            if (keptTotal >= TOPK) break;
            if (nrem <= m) { nrem = 0; break; }
            __syncthreads();   // s_kbox ready; also guards sbox reads below

            // 4) fused suppress (vs nk kept, early-exit) + stable compact
            int newbase = 0;
            for (int start = m; start < nrem; start += NMS_NT) {
                int j = start + tid;
                bool ok = (j < nrem);
                float key = 0.0f, ar = 0.0f; float4 bx;
                if (ok) {
                    key = sscore[j]; bx = sbox[j]; ar = sarea[j];
                    for (int t = 0; t < nk; t++) {
                        if (overlap_f(s_kbox[t], s_karea[t], bx, ar)) {
                            ok = false; break;
                        }
                    }
                }
                unsigned b = __ballot_sync(0xffffffffu, ok);
                if (lane == 0) s_wcnt[wid] = __popc(b);
                __syncthreads();          // reads done; safe to write
                int wpre, wsum;
                scan_counts(s_wcnt, wid, lane, wpre, wsum);
                int rank = newbase + wpre + __popc(b & lmask);
                if (ok) { sscore[rank] = key; sbox[rank] = bx; sarea[rank] = ar; }
                newbase += wsum;
                __syncthreads();
            }
            nrem = newbase;
        }
    }

    // pad unused candidate slots; publish kept count
    int kc = min(keptTotal, TOPK);
    for (int r = kc + tid; r < TOPK; r += NMS_NT)
        g_candScore[img][c][r] = -INFINITY;
    if (tid == 0) g_candCnt[img][c] = keptTotal;
}

// ---------------- kernel 3: per-image rank-based parallel top-200 -------------
#define TKR_NT 1024
__global__ void __launch_bounds__(TKR_NT, 1)
topk_rank_kernel(float* __restrict__ out)
{
    __shared__ float ssc[NCLS * TOPK];
    __shared__ int   s_total;

    int img = blockIdx.x;
    int tid = threadIdx.x;

    const float* src = &g_candScore[img][0][0];
    for (int t = tid; t < NCLS * TOPK; t += TKR_NT)
        ssc[t] = src[t];
    if (tid == 0) {
        int tt = 0;
        for (int c = 0; c < NCLS; c++) tt += g_candCnt[img][c];
        s_total = tt;
    }
    __syncthreads();

    int found = min(s_total, TOPK);

    float* outBoxes  = out;                                     // [4,200,4]
    float* outLabels = out + NIMG * TOPK * 4;                   // [4,200]
    float* outScores = out + NIMG * TOPK * 4 + NIMG * TOPK;     // [4,200]
    float* outCount  = out + NIMG * TOPK * 4 + 2 * NIMG * TOPK; // [4]

    // defaults for slots [found, TOPK)
    for (int k = found + tid; k < TOPK; k += TKR_NT) {
        int basei = (img * TOPK + k) * 4;
        outBoxes[basei + 0] = 0.0f;
        outBoxes[basei + 1] = 0.0f;
        outBoxes[basei + 2] = 0.0f;
        outBoxes[basei + 3] = 0.0f;
        outLabels[img * TOPK + k] = 0.0f;
        outScores[img * TOPK + k] = 0.0f;
    }

    // rank computation (slots [0, found) get exactly one writer each)
    for (int e = tid; e < NCLS * TOPK; e += TKR_NT) {
        float ka = ssc[e];
        if (!(ka > -INFINITY)) continue;      // -inf padding
        int ca = e / TOPK;
        int ra = e - ca * TOPK;
        int rank = ra;
        for (int c2 = 0; c2 < NCLS && rank < TOPK; c2++) {
            if (c2 == ca) continue;
            const float* L = ssc + c2 * TOPK;
            int lo = 0, hi = TOPK;
            if (c2 < ca) {
                while (lo < hi) {             // count >= ka
                    int mid = (lo + hi) >> 1;
                    if (L[mid] >= ka) lo = mid + 1; else hi = mid;
                }
            } else {
                while (lo < hi) {             // count > ka
                    int mid = (lo + hi) >> 1;
                    if (L[mid] > ka) lo = mid + 1; else hi = mid;
                }
            }
            rank += lo;
        }
        if (rank < TOPK) {
            float4 b = g_candBox[img][ca][ra];
            int basei = (img * TOPK + rank) * 4;
            outBoxes[basei + 0] = b.x;
            outBoxes[basei + 1] = b.y;
            outBoxes[basei + 2] = b.z;
            outBoxes[basei + 3] = b.w;
            outLabels[img * TOPK + rank] = (float)(ca + 1);
            outScores[img * TOPK + rank] = ka;
        }
    }
    __syncthreads();

    if (tid == 0) {
        int cnt = found;
        if (cnt == 0) {
            int basei = img * TOPK * 4;
            outBoxes[basei + 0] = 0.0f;
            outBoxes[basei + 1] = 0.0f;
            outBoxes[basei + 2] = 1.0f;
            outBoxes[basei + 3] = 1.0f;
            cnt = 1;
        }
        outCount[img] = (float)cnt;
    }
}

// ---------------- launch ----------------
extern "C" void kernel_launch(void* const* d_in, const int* in_sizes, int n_in,
                              void* d_out, int out_size)
{
    const float* locs   = (const float*)d_in[0];  // (4,3106,4)
    const float* scores = (const float*)d_in[1];  // (4,3106,21)
    const float* priors = (const float*)d_in[2];  // (3106,4)
    float* out = (float*)d_out;

    static bool attr_set = false;
    if (!attr_set) {
        cudaFuncSetAttribute(nms_kernel,
                             cudaFuncAttributeMaxDynamicSharedMemorySize,
                             SMEM_NMS_BYTES);
        attr_set = true;
    }

    int threads2 = NIMG * NPRI * 2;               // 2 threads per row
    softmax_decode_kernel<<<(threads2 + 63) / 64, 64>>>(locs, scores, priors);
    nms_kernel<<<NIMG * NCLS, NMS_NT, SMEM_NMS_BYTES>>>();
    topk_rank_kernel<<<NIMG, TKR_NT>>>(out);
}

// round 16
// speedup vs baseline: 1.2896x; 1.2896x over previous
#include <cuda_runtime.h>
#include <math.h>
#include <limits.h>

#define NIMG 4
#define NPRI 3106
#define NCLS 20      // classes 1..20 (background excluded)
#define NTOT 21
#define NPAD 4096    // max pow2 bound for sort array
#define TOPK 200

#define MIN_SCORE 0.05f
#define MAX_OVERLAP 0.45f

#define NMS_NT 1024
#define NWARPS (NMS_NT / 32)   // 32

#define CHUNK 64

// ---------------- device scratch (no allocations allowed) ----------------
__device__ float  g_cls[NIMG][NCLS][NPRI];      // class-major probs
__device__ float4 g_box[NIMG][NPRI];            // decoded boxes x1,y1,x2,y2
__device__ float  g_candScore[NIMG][NCLS][TOPK];
__device__ float4 g_candBox[NIMG][NCLS][TOPK];
__device__ int    g_candCnt[NIMG][NCLS];

// Accurate fp32 exp via fp64 range-reduction + compensated (double-float)
// fp32 Horner. Relative error ~2^-45. Immune to fast-math. |x| <= 85.
__device__ __forceinline__ float exp_ff(float x)
{
    float nf = rintf(x * 1.4426950408889634f);
    double rd = fma((double)nf, -0.6931471805599453, (double)x);
    float rh = (float)rd;
    float rl = (float)(rd - (double)rh);

    float t;
    t = 2.0876756987868099e-9f;                    // 1/12!
    t = fmaf(t, rh, 2.5052108385441720e-8f);       // 1/11!
    t = fmaf(t, rh, 2.7557319223985893e-7f);       // 1/10!
    t = fmaf(t, rh, 2.7557319223985888e-6f);       // 1/9!
    t = fmaf(t, rh, 2.4801587301587302e-5f);       // 1/8!
    t = fmaf(t, rh, 1.9841269841269841e-4f);       // 1/7!

    const float C[7] = { 1.3888888888888889e-3f,
                         8.3333333333333332e-3f,
                         4.1666666666666664e-2f,
                         1.6666666666666666e-1f,
                         0.5f, 1.0f, 1.0f };
    float ah = t, al = 0.0f;
    #pragma unroll
    for (int k = 0; k < 7; k++) {
        float ph = __fmul_rn(ah, rh);
        float pl = fmaf(ah, rh, -ph);
        pl = fmaf(al, rh, pl);
        float ck = C[k];
        float sh = __fadd_rn(ck, ph);
        float sl = __fsub_rn(ph, __fsub_rn(sh, ck));
        al = __fadd_rn(pl, sl);
        ah = sh;
    }
    float res = __fadd_rn(fmaf(ah, rl, al), ah);
    return res * __int_as_float(((int)nf + 127) << 23);
}

// ---------------- kernel 1: softmax + box decode (8 threads per row) ---------
// lane k of each 8-group handles classes {k, k+8, k+16(<21)}; decode exps on
// lanes 5/6 (2-class lanes). Max/sum via 3 xor-shfls within the 8-group.
__global__ void __launch_bounds__(256, 1)
softmax_decode_kernel(const float* __restrict__ locs,
                      const float* __restrict__ scores,
                      const float* __restrict__ priors)
{
    int gid = blockIdx.x * blockDim.x + threadIdx.x;
    int row = gid >> 3;
    int sub = gid & 7;
    bool real = (row < NIMG * NPRI);
    if (!real) row = NIMG * NPRI - 1;      // clamp; keep lanes alive for shfl
    int img = row / NPRI;
    int p   = row - img * NPRI;

    const float* s  = scores + (size_t)row * NTOT;
    const float* l  = locs   + (size_t)row * 4;
    const float* pr = priors + (size_t)p * 4;

    bool has2 = (sub < 5);                  // class sub+16 exists (16..20)
    float z0 = s[sub];
    float z1 = s[sub + 8];
    float z2 = has2 ? s[sub + 16] : -INFINITY;

    float m = fmaxf(fmaxf(z0, z1), z2);
    m = fmaxf(m, __shfl_xor_sync(0xffffffffu, m, 1));
    m = fmaxf(m, __shfl_xor_sync(0xffffffffu, m, 2));
    m = fmaxf(m, __shfl_xor_sync(0xffffffffu, m, 4));

    float e0 = exp_ff(z0 - m);
    float e1 = exp_ff(z1 - m);
    float e2 = has2 ? exp_ff(z2 - m) : 0.0f;

    double dsum = (double)e0 + (double)e1 + (double)e2;

    // decode exps in parallel on the lighter lanes
    float dexp = 0.0f;
    if (sub == 5)      dexp = exp_ff(__fdiv_rn(l[2], 5.0f)) * pr[2];
    else if (sub == 6) dexp = exp_ff(__fdiv_rn(l[3], 5.0f)) * pr[3];

    dsum += __shfl_xor_sync(0xffffffffu, dsum, 1);
    dsum += __shfl_xor_sync(0xffffffffu, dsum, 2);
    dsum += __shfl_xor_sync(0xffffffffu, dsum, 4);
    float fsum = (float)dsum;

    if (real) {
        if (sub >= 1)                        // skip background class 0
            g_cls[img][sub - 1][p] = __fdiv_rn(e0, fsum);
        g_cls[img][sub + 7][p] = __fdiv_rn(e1, fsum);          // class sub+8
        if (has2)
            g_cls[img][sub + 15][p] = __fdiv_rn(e2, fsum);     // class sub+16
    }

    float w = __shfl_sync(0xffffffffu, dexp, 5, 8);   // from group lane 5
    float h = __shfl_sync(0xffffffffu, dexp, 6, 8);   // from group lane 6
    if (real && sub == 0) {
        float cx = __fdiv_rn(l[0] * pr[2], 10.0f) + pr[0];
        float cy = __fdiv_rn(l[1] * pr[3], 10.0f) + pr[1];
        float4 b;
        b.x = cx - __fdiv_rn(w, 2.0f);
        b.y = cy - __fdiv_rn(h, 2.0f);
        b.z = cx + __fdiv_rn(w, 2.0f);
        b.w = cy + __fdiv_rn(h, 2.0f);
        g_box[img][p] = b;
    }
}

// overlap test with precomputed areas; bit-identical to reference iou > T
__device__ __forceinline__ bool overlap_f(float4 a, float aA, float4 b, float aB)
{
    float dx = fminf(a.z, b.z) - fmaxf(a.x, b.x);
    float dy = fminf(a.w, b.w) - fmaxf(a.y, b.y);
    if (dx > 0.0f && dy > 0.0f) {
        float inter = dx * dy;
        return __fdiv_rn(inter, aA + aB - inter) > MAX_OVERLAP;
    }
    return false;   // inter==0 -> iou==0 <= T
}

// exclusive warp-count prefix via shfl scan; s_wcnt[lane] valid for lane<32.
__device__ __forceinline__ void scan_counts(const int* s_wcnt, int wid, int lane,
                                            int& wpre, int& wsum)
{
    int x = s_wcnt[lane];
    #pragma unroll
    for (int d = 1; d < 32; d <<= 1) {
        int v = __shfl_up_sync(0xffffffffu, x, d);
        if (lane >= d) x += v;
    }
    wsum = __shfl_sync(0xffffffffu, x, 31);
    wpre = (wid == 0) ? 0 : __shfl_sync(0xffffffffu, x, wid - 1);
}

// one register-resident bitonic micro-step on value v at element index e
__device__ __forceinline__ unsigned long long bitonic_reg_step(
    unsigned long long v, int e, int k, int j)
{
    unsigned long long pv = __shfl_xor_sync(0xffffffffu, v, j);
    bool down  = ((e & k) == 0);     // this region sorts descending
    bool lower = ((e & j) == 0);
    unsigned long long mx = (v > pv) ? v : pv;
    unsigned long long mn = (v > pv) ? pv : v;
    return (down == lower) ? mx : mn;
}

// ---------------- kernel 2: per-(image,class) greedy NMS ----------------
// Dynamic shared layout:
//   [0,      32768)   u64    skey64[NPAD]      (score_bits<<32 | ~idx)
//   [32768,  82464)   float4 sbox[NPRI]
//   [82464,  94888)   float  sscore[NPRI]
//   [94888, 107312)   float  sarea[NPRI]
#define SMEM_NMS_BYTES 107392

__global__ void __launch_bounds__(NMS_NT, 1)
nms_kernel()
{
    extern __shared__ char sm[];
    unsigned long long* skey64 = (unsigned long long*)(sm);
    float4*             sbox   = (float4*)(sm + 32768);
    float*              sscore = (float*)(sm + 82464);
    float*              sarea  = (float*)(sm + 94888);
    __shared__ int      s_wcnt[NWARPS];
    __shared__ unsigned s_row[CHUNK][2];
    __shared__ unsigned s_keptw[2];
    __shared__ int      s_nk;
    __shared__ float4   s_kbox[CHUNK];
    __shared__ float    s_karea[CHUNK];

    int img  = blockIdx.x / NCLS;
    int c    = blockIdx.x % NCLS;
    int tid  = threadIdx.x;
    int wid  = tid >> 5;
    int lane = tid & 31;
    unsigned lmask = (1u << lane) - 1u;

    // ---- Phase A: stable compaction of valid entries ----
    int base = 0;
    for (int bp = 0; bp < NPRI; bp += NMS_NT) {
        int p = bp + tid;
        float sc = (p < NPRI) ? g_cls[img][c][p] : 0.0f;
        bool ok = (p < NPRI) && (sc > MIN_SCORE);
        unsigned b = __ballot_sync(0xffffffffu, ok);
        if (lane == 0) s_wcnt[wid] = __popc(b);
        __syncthreads();
        int wpre, wsum;
        scan_counts(s_wcnt, wid, lane, wpre, wsum);
        int rank = base + wpre + __popc(b & lmask);
        if (ok)
            skey64[rank] = ((unsigned long long)__float_as_uint(sc) << 32)
                         | (unsigned int)(~p);
        base += wsum;
        __syncthreads();
    }
    int nvalid = base;

    int keptTotal = 0;

    if (nvalid > 0) {
        int npow = 32;
        while (npow < nvalid) npow <<= 1;
        for (int t = nvalid + tid; t < npow; t += NMS_NT)
            skey64[t] = 0ull;
        __syncthreads();

        // ---- Phase B: HYBRID bitonic sort (desc u64; score desc, idx asc) ----
        int nseg = (npow + NMS_NT - 1) / NMS_NT;

        // stages k = 2..32: entirely intra-warp (register + shfl)
        for (int q = 0; q < nseg; q++) {
            int e = q * NMS_NT + tid;
            if (e < npow) {               // whole warp uniform (npow % 32 == 0)
                unsigned long long v = skey64[e];
                #pragma unroll
                for (int k = 2; k <= 32; k <<= 1) {
                    #pragma unroll
                    for (int j = k >> 1; j >= 1; j >>= 1)
                        v = bitonic_reg_step(v, e, k, j);
                }
                skey64[e] = v;
            }
        }
        __syncthreads();

        // stages k = 64..npow: smem steps for j>=32, register tail j<=16
        for (int k = 64; k <= npow; k <<= 1) {
            for (int j = k >> 1; j >= 32; j >>= 1) {
                for (int t = tid; t < npow; t += NMS_NT) {
                    int l = t ^ j;
                    if (l > t) {
                        unsigned long long ka = skey64[t], kb = skey64[l];
                        bool asc = ((t & k) == 0);
                        if ((kb > ka) == asc) {
                            skey64[t] = kb;
                            skey64[l] = ka;
                        }
                    }
                }
                __syncthreads();
            }
            for (int q = 0; q < nseg; q++) {
                int e = q * NMS_NT + tid;
                if (e < npow) {
                    unsigned long long v = skey64[e];
                    #pragma unroll
                    for (int j = 16; j >= 1; j >>= 1)
                        v = bitonic_reg_step(v, e, k, j);
                    skey64[e] = v;
                }
            }
            __syncthreads();
        }

        // ---- Phase C: gather boxes + scores + areas ----
        for (int i = tid; i < nvalid; i += NMS_NT) {
            unsigned long long key = skey64[i];
            unsigned idx = ~((unsigned)key);
            float4 b = g_box[img][idx];
            sbox[i]   = b;
            sscore[i] = __uint_as_float((unsigned)(key >> 32));
            sarea[i]  = (b.z - b.x) * (b.w - b.y);
        }
        __syncthreads();

        // ---- Phase D: 64-wide chunked greedy ----
        int nrem = nvalid;
        while (nrem > 0 && keptTotal < TOPK) {
            int m = min(CHUNK, nrem);

            // 1) in-chunk upper-tri matrix rows via one-IoU-per-lane + ballot.
            if (wid < m) {
                int r = wid;
                float4 bi = sbox[r];
                float  ai = sarea[r];
                bool ov0 = (lane > r && lane < m)
                         ? overlap_f(bi, ai, sbox[lane], sarea[lane]) : false;
                int j2 = lane + 32;
                bool ov1 = (j2 < m)
                         ? overlap_f(bi, ai, sbox[j2], sarea[j2]) : false;
                unsigned w0 = __ballot_sync(0xffffffffu, ov0);
                unsigned w1 = __ballot_sync(0xffffffffu, ov1);
                if (lane == 0) { s_row[r][0] = w0; s_row[r][1] = w1; }
            }
            {
                int r2 = wid + 32;
                if (r2 < m) {
                    float4 bi = sbox[r2];
                    float  ai = sarea[r2];
                    int j2 = lane + 32;
                    bool ov = (j2 > r2 && j2 < m)
                            ? overlap_f(bi, ai, sbox[j2], sarea[j2]) : false;
                    unsigned w1 = __ballot_sync(0xffffffffu, ov);
                    if (lane == 0) { s_row[r2][0] = 0u; s_row[r2][1] = w1; }
                }
            }
            __syncthreads();

            // 2) warp 0: ballot resolve with lane-held row masks (no IoU,
            //    iterations = number of kept boxes only)
            if (wid == 0) {
                unsigned r0w0 = 0u, r0w1 = 0u, r1w1 = 0u;
                if (lane < m)      { r0w0 = s_row[lane][0]; r0w1 = s_row[lane][1]; }
                if (lane + 32 < m)   r1w1 = s_row[lane + 32][1];
                unsigned valid0 = (m >= 32) ? 0xffffffffu : ((1u << m) - 1u);
                unsigned valid1 = (m > 32)
                                ? ((m >= 64) ? 0xffffffffu : ((1u << (m - 32)) - 1u))
                                : 0u;
                unsigned sup1 = 0u, kept0 = 0u, kept1 = 0u;
                unsigned unres = valid0;
                while (unres) {
                    int i = __ffs(unres) - 1;
                    kept0 |= 1u << i;
                    unsigned ri0 = __shfl_sync(0xffffffffu, r0w0, i);
                    unsigned ri1 = __shfl_sync(0xffffffffu, r0w1, i);
                    sup1 |= ri1;
                    unres &= ~(ri0 | (1u << i));
                }
                unres = valid1 & ~sup1;
                while (unres) {
                    int i = __ffs(unres) - 1;
                    kept1 |= 1u << i;
                    unsigned ri1 = __shfl_sync(0xffffffffu, r1w1, i);
                    unres &= ~(ri1 | (1u << i));
                }
                if (lane == 0) {
                    s_keptw[0] = kept0;
                    s_keptw[1] = kept1;
                    s_nk = __popc(kept0) + __popc(kept1);
                }
            }
            __syncthreads();

            int nk = s_nk;

            // 3) export kept + densify kept boxes via keptw ranks
            if (tid < m) {
                int w = tid >> 5;
                unsigned km = s_keptw[w];
                if ((km >> lane) & 1u) {
                    int rank = ((w == 1) ? __popc(s_keptw[0]) : 0)
                             + __popc(km & lmask);
                    int slot = keptTotal + rank;
                    if (slot < TOPK) {
                        g_candScore[img][c][slot] = sscore[tid];
                        g_candBox[img][c][slot]   = sbox[tid];
                    }
                    s_kbox[rank]  = sbox[tid];
                    s_karea[rank] = sarea[tid];
                }
            }
            keptTotal += nk;
            if (keptTotal >= TOPK) break;
            if (nrem <= m) { nrem = 0; break; }
            __syncthreads();   // s_kbox ready; also guards sbox reads below

            // 4) fused suppress (vs nk kept, early-exit) + stable compact
            int newbase = 0;
            for (int start = m; start < nrem; start += NMS_NT) {
                int j = start + tid;
                bool ok = (j < nrem);
                float key = 0.0f, ar = 0.0f; float4 bx;
                if (ok) {
                    key = sscore[j]; bx = sbox[j]; ar = sarea[j];
                    for (int t = 0; t < nk; t++) {
                        if (overlap_f(s_kbox[t], s_karea[t], bx, ar)) {
                            ok = false; break;
                        }
                    }
                }
                unsigned b = __ballot_sync(0xffffffffu, ok);
                if (lane == 0) s_wcnt[wid] = __popc(b);
                __syncthreads();          // reads done; safe to write
                int wpre, wsum;
                scan_counts(s_wcnt, wid, lane, wpre, wsum);
                int rank = newbase + wpre + __popc(b & lmask);
                if (ok) { sscore[rank] = key; sbox[rank] = bx; sarea[rank] = ar; }
                newbase += wsum;
                __syncthreads();
            }
            nrem = newbase;
        }
    }

    // pad unused candidate slots; publish kept count
    int kc = min(keptTotal, TOPK);
    for (int r = kc + tid; r < TOPK; r += NMS_NT)
        g_candScore[img][c][r] = -INFINITY;
    if (tid == 0) g_candCnt[img][c] = keptTotal;
}

// ---------------- kernel 3: per-image rank-based parallel top-200 -------------
#define TKR_NT 1024
__global__ void __launch_bounds__(TKR_NT, 1)
topk_rank_kernel(float* __restrict__ out)
{
    __shared__ float ssc[NCLS * TOPK];
    __shared__ int   s_total;

    int img = blockIdx.x;
    int tid = threadIdx.x;

    const float* src = &g_candScore[img][0][0];
    for (int t = tid; t < NCLS * TOPK; t += TKR_NT)
        ssc[t] = src[t];
    if (tid == 0) {
        int tt = 0;
        for (int c = 0; c < NCLS; c++) tt += g_candCnt[img][c];
        s_total = tt;
    }
    __syncthreads();

    int found = min(s_total, TOPK);

    float* outBoxes  = out;                                     // [4,200,4]
    float* outLabels = out + NIMG * TOPK * 4;                   // [4,200]
    float* outScores = out + NIMG * TOPK * 4 + NIMG * TOPK;     // [4,200]
    float* outCount  = out + NIMG * TOPK * 4 + 2 * NIMG * TOPK; // [4]

    // defaults for slots [found, TOPK)
    for (int k = found + tid; k < TOPK; k += TKR_NT) {
        int basei = (img * TOPK + k) * 4;
        outBoxes[basei + 0] = 0.0f;
        outBoxes[basei + 1] = 0.0f;
        outBoxes[basei + 2] = 0.0f;
        outBoxes[basei + 3] = 0.0f;
        outLabels[img * TOPK + k] = 0.0f;
        outScores[img * TOPK + k] = 0.0f;
    }

    // rank computation (slots [0, found) get exactly one writer each)
    for (int e = tid; e < NCLS * TOPK; e += TKR_NT) {
        float ka = ssc[e];
        if (!(ka > -INFINITY)) continue;      // -inf padding
        int ca = e / TOPK;
        int ra = e - ca * TOPK;
        int rank = ra;
        for (int c2 = 0; c2 < NCLS && rank < TOPK; c2++) {
            if (c2 == ca) continue;
            const float* L = ssc + c2 * TOPK;
            int lo = 0, hi = TOPK;
            if (c2 < ca) {
                while (lo < hi) {             // count >= ka
                    int mid = (lo + hi) >> 1;
                    if (L[mid] >= ka) lo = mid + 1; else hi = mid;
                }
            } else {
                while (lo < hi) {             // count > ka
                    int mid = (lo + hi) >> 1;
                    if (L[mid] > ka) lo = mid + 1; else hi = mid;
                }
            }
            rank += lo;
        }
        if (rank < TOPK) {
            float4 b = g_candBox[img][ca][ra];
            int basei = (img * TOPK + rank) * 4;
            outBoxes[basei + 0] = b.x;
            outBoxes[basei + 1] = b.y;
            outBoxes[basei + 2] = b.z;
            outBoxes[basei + 3] = b.w;
            outLabels[img * TOPK + rank] = (float)(ca + 1);
            outScores[img * TOPK + rank] = ka;
        }
    }
    __syncthreads();

    if (tid == 0) {
        int cnt = found;
        if (cnt == 0) {
            int basei = img * TOPK * 4;
            outBoxes[basei + 0] = 0.0f;
            outBoxes[basei + 1] = 0.0f;
            outBoxes[basei + 2] = 1.0f;
            outBoxes[basei + 3] = 1.0f;
            cnt = 1;
        }
        outCount[img] = (float)cnt;
    }
}

// ---------------- launch ----------------
extern "C" void kernel_launch(void* const* d_in, const int* in_sizes, int n_in,
                              void* d_out, int out_size)
{
    const float* locs   = (const float*)d_in[0];  // (4,3106,4)
    const float* scores = (const float*)d_in[1];  // (4,3106,21)
    const float* priors = (const float*)d_in[2];  // (3106,4)
    float* out = (float*)d_out;

    static bool attr_set = false;
    if (!attr_set) {
        cudaFuncSetAttribute(nms_kernel,
                             cudaFuncAttributeMaxDynamicSharedMemorySize,
                             SMEM_NMS_BYTES);
        attr_set = true;
    }

    int threads8 = NIMG * NPRI * 8;               // 8 threads per row
    softmax_decode_kernel<<<(threads8 + 255) / 256, 256>>>(locs, scores, priors);
    nms_kernel<<<NIMG * NCLS, NMS_NT, SMEM_NMS_BYTES>>>();
    topk_rank_kernel<<<NIMG, TKR_NT>>>(out);
}

// round 17
// speedup vs baseline: 1.3209x; 1.0243x over previous
#include <cuda_runtime.h>
#include <math.h>
#include <limits.h>

#define NIMG 4
#define NPRI 3106
#define NCLS 20      // classes 1..20 (background excluded)
#define NTOT 21
#define NPAD 4096    // max pow2 bound for sort array
#define TOPK 200

#define MIN_SCORE 0.05f
#define MAX_OVERLAP 0.45f

#define NMS_NT 1024
#define NWARPS (NMS_NT / 32)   // 32

#define CHUNK 64

// ---------------- device scratch (no allocations allowed) ----------------
__device__ float  g_cls[NIMG][NCLS][NPRI];      // class-major probs
__device__ float4 g_box[NIMG][NPRI];            // decoded boxes x1,y1,x2,y2
__device__ float  g_candScore[NIMG][NCLS][TOPK];
__device__ float4 g_candBox[NIMG][NCLS][TOPK];
__device__ int    g_candCnt[NIMG][NCLS];

// Accurate fp32 exp via fp64 range-reduction + compensated (double-float)
// fp32 Horner. Relative error ~2^-45. Immune to fast-math. |x| <= 85.
__device__ __forceinline__ float exp_ff(float x)
{
    float nf = rintf(x * 1.4426950408889634f);
    double rd = fma((double)nf, -0.6931471805599453, (double)x);
    float rh = (float)rd;
    float rl = (float)(rd - (double)rh);

    float t;
    t = 2.0876756987868099e-9f;                    // 1/12!
    t = fmaf(t, rh, 2.5052108385441720e-8f);       // 1/11!
    t = fmaf(t, rh, 2.7557319223985893e-7f);       // 1/10!
    t = fmaf(t, rh, 2.7557319223985888e-6f);       // 1/9!
    t = fmaf(t, rh, 2.4801587301587302e-5f);       // 1/8!
    t = fmaf(t, rh, 1.9841269841269841e-4f);       // 1/7!

    const float C[7] = { 1.3888888888888889e-3f,
                         8.3333333333333332e-3f,
                         4.1666666666666664e-2f,
                         1.6666666666666666e-1f,
                         0.5f, 1.0f, 1.0f };
    float ah = t, al = 0.0f;
    #pragma unroll
    for (int k = 0; k < 7; k++) {
        float ph = __fmul_rn(ah, rh);
        float pl = fmaf(ah, rh, -ph);
        pl = fmaf(al, rh, pl);
        float ck = C[k];
        float sh = __fadd_rn(ck, ph);
        float sl = __fsub_rn(ph, __fsub_rn(sh, ck));
        al = __fadd_rn(pl, sl);
        ah = sh;
    }
    float res = __fadd_rn(fmaf(ah, rl, al), ah);
    return res * __int_as_float(((int)nf + 127) << 23);
}

// ---------------- kernel 1: softmax + box decode (2 threads per row) ----------
__global__ void __launch_bounds__(64, 1)
softmax_decode_kernel(const float* __restrict__ locs,
                      const float* __restrict__ scores,
                      const float* __restrict__ priors)
{
    int gid  = blockIdx.x * blockDim.x + threadIdx.x;
    int row  = gid >> 1;
    int half = gid & 1;
    bool real = (row < NIMG * NPRI);
    if (!real) row = NIMG * NPRI - 1;          // clamp; keep lanes alive for shfl
    int img = row / NPRI;
    int p   = row - img * NPRI;

    const float* s  = scores + (size_t)row * NTOT;
    const float* l  = locs   + (size_t)row * 4;
    const float* pr = priors + (size_t)p * 4;

    // half0: classes 0..10 (11), half1: classes 11..20 (10)
    int c0 = half ? 11 : 0;
    int cn = half ? 10 : 11;

    float zv[11];
    float m = -INFINITY;
    #pragma unroll
    for (int k = 0; k < 11; k++) {
        if (k < cn) { zv[k] = s[c0 + k]; m = fmaxf(m, zv[k]); }
    }
    m = fmaxf(m, __shfl_xor_sync(0xffffffffu, m, 1));

    float e[11];
    double dsum = 0.0;
    #pragma unroll
    for (int k = 0; k < 11; k++) {
        if (k < cn) { e[k] = exp_ff(zv[k] - m); dsum += (double)e[k]; }
    }
    // decode exp in parallel: half0 -> w, half1 -> h
    float dexp = half ? (exp_ff(__fdiv_rn(l[3], 5.0f)) * pr[3])
                      : (exp_ff(__fdiv_rn(l[2], 5.0f)) * pr[2]);

    dsum += __shfl_xor_sync(0xffffffffu, dsum, 1);
    float fsum = (float)dsum;

    if (real) {
        if (half == 0) {
            #pragma unroll
            for (int k = 1; k < 11; k++)          // skip background class 0
                g_cls[img][k - 1][p] = __fdiv_rn(e[k], fsum);
        } else {
            #pragma unroll
            for (int k = 0; k < 10; k++)
                g_cls[img][10 + k][p] = __fdiv_rn(e[k], fsum);
        }
    }

    float other = __shfl_xor_sync(0xffffffffu, dexp, 1);
    if (real && half == 0) {
        float w = dexp, h = other;
        float cx = __fdiv_rn(l[0] * pr[2], 10.0f) + pr[0];
        float cy = __fdiv_rn(l[1] * pr[3], 10.0f) + pr[1];
        float4 b;
        b.x = cx - __fdiv_rn(w, 2.0f);
        b.y = cy - __fdiv_rn(h, 2.0f);
        b.z = cx + __fdiv_rn(w, 2.0f);
        b.w = cy + __fdiv_rn(h, 2.0f);
        g_box[img][p] = b;
    }
}

// overlap test with precomputed areas; bit-identical to reference iou > T
__device__ __forceinline__ bool overlap_f(float4 a, float aA, float4 b, float aB)
{
    float dx = fminf(a.z, b.z) - fmaxf(a.x, b.x);
    float dy = fminf(a.w, b.w) - fmaxf(a.y, b.y);
    if (dx > 0.0f && dy > 0.0f) {
        float inter = dx * dy;
        return __fdiv_rn(inter, aA + aB - inter) > MAX_OVERLAP;
    }
    return false;   // inter==0 -> iou==0 <= T
}

// exclusive warp-count prefix via shfl scan; s_wcnt[lane] valid for lane<32.
__device__ __forceinline__ void scan_counts(const int* s_wcnt, int wid, int lane,
                                            int& wpre, int& wsum)
{
    int x = s_wcnt[lane];
    #pragma unroll
    for (int d = 1; d < 32; d <<= 1) {
        int v = __shfl_up_sync(0xffffffffu, x, d);
        if (lane >= d) x += v;
    }
    wsum = __shfl_sync(0xffffffffu, x, 31);
    wpre = (wid == 0) ? 0 : __shfl_sync(0xffffffffu, x, wid - 1);
}

// one register-resident bitonic micro-step on value v at element index e
__device__ __forceinline__ unsigned long long bitonic_reg_step(
    unsigned long long v, int e, int k, int j)
{
    unsigned long long pv = __shfl_xor_sync(0xffffffffu, v, j);
    bool down  = ((e & k) == 0);     // this region sorts descending
    bool lower = ((e & j) == 0);
    unsigned long long mx = (v > pv) ? v : pv;
    unsigned long long mn = (v > pv) ? pv : v;
    return (down == lower) ? mx : mn;
}

// ---------------- kernel 2: per-(image,class) greedy NMS ----------------
// Dynamic shared layout:
//   [0,      32768)   u64    skey64[NPAD]      (score_bits<<32 | ~idx)
//   [32768,  82464)   float4 sbox[NPRI]
//   [82464, 107312)   float2 ssa[NPRI]         ({score, area})
#define SMEM_NMS_BYTES 107392

__global__ void __launch_bounds__(NMS_NT, 1)
nms_kernel()
{
    extern __shared__ char sm[];
    unsigned long long* skey64 = (unsigned long long*)(sm);
    float4*             sbox   = (float4*)(sm + 32768);
    float2*             ssa    = (float2*)(sm + 82464);
    __shared__ int      s_wcnt[NWARPS];
    __shared__ int      s_nk;
    __shared__ float4   s_kbox[CHUNK];
    __shared__ float    s_karea[CHUNK];
    __shared__ unsigned s_row[CHUNK][2];

    int img  = blockIdx.x / NCLS;
    int c    = blockIdx.x % NCLS;
    int tid  = threadIdx.x;
    int wid  = tid >> 5;
    int lane = tid & 31;
    unsigned lmask = (1u << lane) - 1u;

    // ---- Phase A: stable compaction of valid entries ----
    int base = 0;
    for (int bp = 0; bp < NPRI; bp += NMS_NT) {
        int p = bp + tid;
        float sc = (p < NPRI) ? g_cls[img][c][p] : 0.0f;
        bool ok = (p < NPRI) && (sc > MIN_SCORE);
        unsigned b = __ballot_sync(0xffffffffu, ok);
        if (lane == 0) s_wcnt[wid] = __popc(b);
        __syncthreads();
        int wpre, wsum;
        scan_counts(s_wcnt, wid, lane, wpre, wsum);
        int rank = base + wpre + __popc(b & lmask);
        if (ok)
            skey64[rank] = ((unsigned long long)__float_as_uint(sc) << 32)
                         | (unsigned int)(~p);
        base += wsum;
        __syncthreads();
    }
    int nvalid = base;

    int keptTotal = 0;

    if (nvalid > 0) {
        int npow = 32;
        while (npow < nvalid) npow <<= 1;
        for (int t = nvalid + tid; t < npow; t += NMS_NT)
            skey64[t] = 0ull;
        __syncthreads();

        // ---- Phase B: HYBRID bitonic sort (desc u64; score desc, idx asc) ----
        int nseg = (npow + NMS_NT - 1) / NMS_NT;

        // stages k = 2..32: entirely intra-warp (register + shfl)
        for (int q = 0; q < nseg; q++) {
            int e = q * NMS_NT + tid;
            if (e < npow) {               // whole warp uniform (npow % 32 == 0)
                unsigned long long v = skey64[e];
                #pragma unroll
                for (int k = 2; k <= 32; k <<= 1) {
                    #pragma unroll
                    for (int j = k >> 1; j >= 1; j >>= 1)
                        v = bitonic_reg_step(v, e, k, j);
                }
                skey64[e] = v;
            }
        }
        __syncthreads();

        // stages k = 64..npow: smem steps for j>=32, register tail j<=16
        for (int k = 64; k <= npow; k <<= 1) {
            for (int j = k >> 1; j >= 32; j >>= 1) {
                for (int t = tid; t < npow; t += NMS_NT) {
                    int l = t ^ j;
                    if (l > t) {
                        unsigned long long ka = skey64[t], kb = skey64[l];
                        bool asc = ((t & k) == 0);
                        if ((kb > ka) == asc) {
                            skey64[t] = kb;
                            skey64[l] = ka;
                        }
                    }
                }
                __syncthreads();
            }
            for (int q = 0; q < nseg; q++) {
                int e = q * NMS_NT + tid;
                if (e < npow) {
                    unsigned long long v = skey64[e];
                    #pragma unroll
                    for (int j = 16; j >= 1; j >>= 1)
                        v = bitonic_reg_step(v, e, k, j);
                    skey64[e] = v;
                }
            }
            __syncthreads();
        }

        // ---- Phase C: gather boxes + {score, area} ----
        for (int i = tid; i < nvalid; i += NMS_NT) {
            unsigned long long key = skey64[i];
            unsigned idx = ~((unsigned)key);
            float4 b = g_box[img][idx];
            sbox[i] = b;
            float2 sa;
            sa.x = __uint_as_float((unsigned)(key >> 32));
            sa.y = (b.z - b.x) * (b.w - b.y);
            ssa[i] = sa;
        }
        __syncthreads();

        // ---- Phase D: 64-wide chunked greedy ----
        int nrem = nvalid;
        while (nrem > 0 && keptTotal < TOPK) {
            int m = min(CHUNK, nrem);

            // 1) in-chunk upper-tri matrix rows via one-IoU-per-lane + ballot.
            if (wid < m) {
                int r = wid;
                float4 bi = sbox[r];
                float  ai = ssa[r].y;
                bool ov0 = (lane > r && lane < m)
                         ? overlap_f(bi, ai, sbox[lane], ssa[lane].y) : false;
                int j2 = lane + 32;
                bool ov1 = (j2 < m)
                         ? overlap_f(bi, ai, sbox[j2], ssa[j2].y) : false;
                unsigned w0 = __ballot_sync(0xffffffffu, ov0);
                unsigned w1 = __ballot_sync(0xffffffffu, ov1);
                if (lane == 0) { s_row[r][0] = w0; s_row[r][1] = w1; }
            }
            {
                int r2 = wid + 32;
                if (r2 < m) {
                    float4 bi = sbox[r2];
                    float  ai = ssa[r2].y;
                    int j2 = lane + 32;
                    bool ov = (j2 > r2 && j2 < m)
                            ? overlap_f(bi, ai, sbox[j2], ssa[j2].y) : false;
                    unsigned w1 = __ballot_sync(0xffffffffu, ov);
                    if (lane == 0) s_row[r2][1] = w1;
                }
            }
            __syncthreads();   // B1: matrix visible to warp 0

            // 2) warp 0: ballot resolve + EXPORT + densify (all in one warp;
            //    removes a block-wide barrier). Iterations = kept count only.
            if (wid == 0) {
                unsigned r0w0 = 0u, r0w1 = 0u, r1w1 = 0u;
                if (lane < m)      { r0w0 = s_row[lane][0]; r0w1 = s_row[lane][1]; }
                if (lane + 32 < m)   r1w1 = s_row[lane + 32][1];
                unsigned valid0 = (m >= 32) ? 0xffffffffu : ((1u << m) - 1u);
                unsigned valid1 = (m > 32)
                                ? ((m >= 64) ? 0xffffffffu : ((1u << (m - 32)) - 1u))
                                : 0u;
                unsigned sup1 = 0u, kept0 = 0u, kept1 = 0u;
                unsigned unres = valid0;
                while (unres) {
                    int i = __ffs(unres) - 1;
                    kept0 |= 1u << i;
                    unsigned ri0 = __shfl_sync(0xffffffffu, r0w0, i);
                    unsigned ri1 = __shfl_sync(0xffffffffu, r0w1, i);
                    sup1 |= ri1;
                    unres &= ~(ri0 | (1u << i));
                }
                unres = valid1 & ~sup1;
                while (unres) {
                    int i = __ffs(unres) - 1;
                    kept1 |= 1u << i;
                    unsigned ri1 = __shfl_sync(0xffffffffu, r1w1, i);
                    unres &= ~(ri1 | (1u << i));
                }
                int nk0 = __popc(kept0);
                // export element `lane`
                if (lane < m && ((kept0 >> lane) & 1u)) {
                    int rank = __popc(kept0 & lmask);
                    int slot = keptTotal + rank;
                    float4 b = sbox[lane];
                    if (slot < TOPK) {
                        g_candScore[img][c][slot] = ssa[lane].x;
                        g_candBox[img][c][slot]   = b;
                    }
                    s_kbox[rank]  = b;
                    s_karea[rank] = ssa[lane].y;
                }
                // export element `lane + 32`
                int i2 = lane + 32;
                if (i2 < m && ((kept1 >> lane) & 1u)) {
                    int rank = nk0 + __popc(kept1 & lmask);
                    int slot = keptTotal + rank;
                    float4 b = sbox[i2];
                    if (slot < TOPK) {
                        g_candScore[img][c][slot] = ssa[i2].x;
                        g_candBox[img][c][slot]   = b;
                    }
                    s_kbox[rank]  = b;
                    s_karea[rank] = ssa[i2].y;
                }
                if (lane == 0) s_nk = nk0 + __popc(kept1);
            }
            __syncthreads();   // B2: s_nk, s_kbox visible; export done

            int nk = s_nk;
            keptTotal += nk;
            if (keptTotal >= TOPK) break;
            if (nrem <= m) { nrem = 0; break; }

            // 3) fused suppress (vs nk kept, early-exit) + stable compact
            int newbase = 0;
            for (int start = m; start < nrem; start += NMS_NT) {
                int j = start + tid;
                bool ok = (j < nrem);
                float2 sa; float4 bx;
                if (ok) {
                    sa = ssa[j]; bx = sbox[j];
                    for (int t = 0; t < nk; t++) {
                        if (overlap_f(s_kbox[t], s_karea[t], bx, sa.y)) {
                            ok = false; break;
                        }
                    }
                }
                unsigned b = __ballot_sync(0xffffffffu, ok);
                if (lane == 0) s_wcnt[wid] = __popc(b);
                __syncthreads();          // B3: reads done; safe to write
                int wpre, wsum;
                scan_counts(s_wcnt, wid, lane, wpre, wsum);
                int rank = newbase + wpre + __popc(b & lmask);
                if (ok) { ssa[rank] = sa; sbox[rank] = bx; }
                newbase += wsum;
                __syncthreads();          // B4: writes visible
            }
            nrem = newbase;
        }
    }

    // pad unused candidate slots; publish kept count
    int kc = min(keptTotal, TOPK);
    for (int r = kc + tid; r < TOPK; r += NMS_NT)
        g_candScore[img][c][r] = -INFINITY;
    if (tid == 0) g_candCnt[img][c] = keptTotal;
}

// ---------------- kernel 3: per-image rank-based parallel top-200 -------------
#define TKR_NT 1024
__global__ void __launch_bounds__(TKR_NT, 1)
topk_rank_kernel(float* __restrict__ out)
{
    __shared__ float ssc[NCLS * TOPK];
    __shared__ int   s_total;

    int img = blockIdx.x;
    int tid = threadIdx.x;

    const float* src = &g_candScore[img][0][0];
    for (int t = tid; t < NCLS * TOPK; t += TKR_NT)
        ssc[t] = src[t];
    if (tid == 0) {
        int tt = 0;
        for (int c = 0; c < NCLS; c++) tt += g_candCnt[img][c];
        s_total = tt;
    }
    __syncthreads();

    int found = min(s_total, TOPK);

    float* outBoxes  = out;                                     // [4,200,4]
    float* outLabels = out + NIMG * TOPK * 4;                   // [4,200]
    float* outScores = out + NIMG * TOPK * 4 + NIMG * TOPK;     // [4,200]
    float* outCount  = out + NIMG * TOPK * 4 + 2 * NIMG * TOPK; // [4]

    // defaults for slots [found, TOPK)
    for (int k = found + tid; k < TOPK; k += TKR_NT) {
        int basei = (img * TOPK + k) * 4;
        outBoxes[basei + 0] = 0.0f;
        outBoxes[basei + 1] = 0.0f;
        outBoxes[basei + 2] = 0.0f;
        outBoxes[basei + 3] = 0.0f;
        outLabels[img * TOPK + k] = 0.0f;
        outScores[img * TOPK + k] = 0.0f;
    }

    // rank computation (slots [0, found) get exactly one writer each)
    for (int e = tid; e < NCLS * TOPK; e += TKR_NT) {
        float ka = ssc[e];
        if (!(ka > -INFINITY)) continue;      // -inf padding
        int ca = e / TOPK;
        int ra = e - ca * TOPK;
        int rank = ra;
        for (int c2 = 0; c2 < NCLS && rank < TOPK; c2++) {
            if (c2 == ca) continue;
            const float* L = ssc + c2 * TOPK;
            int lo = 0, hi = TOPK;
            if (c2 < ca) {
                while (lo < hi) {             // count >= ka
                    int mid = (lo + hi) >> 1;
                    if (L[mid] >= ka) lo = mid + 1; else hi = mid;
                }
            } else {
                while (lo < hi) {             // count > ka
                    int mid = (lo + hi) >> 1;
                    if (L[mid] > ka) lo = mid + 1; else hi = mid;
                }
            }
            rank += lo;
        }
        if (rank < TOPK) {
            float4 b = g_candBox[img][ca][ra];
            int basei = (img * TOPK + rank) * 4;
            outBoxes[basei + 0] = b.x;
            outBoxes[basei + 1] = b.y;
            outBoxes[basei + 2] = b.z;
            outBoxes[basei + 3] = b.w;
            outLabels[img * TOPK + rank] = (float)(ca + 1);
            outScores[img * TOPK + rank] = ka;
        }
    }
    __syncthreads();

    if (tid == 0) {
        int cnt = found;
        if (cnt == 0) {
            int basei = img * TOPK * 4;
            outBoxes[basei + 0] = 0.0f;
            outBoxes[basei + 1] = 0.0f;
            outBoxes[basei + 2] = 1.0f;
            outBoxes[basei + 3] = 1.0f;
            cnt = 1;
        }
        outCount[img] = (float)cnt;
    }
}

// ---------------- launch ----------------
extern "C" void kernel_launch(void* const* d_in, const int* in_sizes, int n_in,
                              void* d_out, int out_size)
{
    const float* locs   = (const float*)d_in[0];  // (4,3106,4)
    const float* scores = (const float*)d_in[1];  // (4,3106,21)
    const float* priors = (const float*)d_in[2];  // (3106,4)
    float* out = (float*)d_out;

    static bool attr_set = false;
    if (!attr_set) {
        cudaFuncSetAttribute(nms_kernel,
                             cudaFuncAttributeMaxDynamicSharedMemorySize,
                             SMEM_NMS_BYTES);
        attr_set = true;
    }

    int threads2 = NIMG * NPRI * 2;               // 2 threads per row
    softmax_decode_kernel<<<(threads2 + 63) / 64, 64>>>(locs, scores, priors);
    nms_kernel<<<NIMG * NCLS, NMS_NT, SMEM_NMS_BYTES>>>();
    topk_rank_kernel<<<NIMG, TKR_NT>>>(out);
}